// round 2
// baseline (speedup 1.0000x reference)
#include <cuda_runtime.h>
#include <cuda_fp16.h>
#include <cstdint>
#include <cstddef>

// Problem constants
#define NTASK 4096   // BS*SL tasks
#define RPC   32     // tasks per CTA
#define NCTA  128    // NTASK / RPC
#define ROWB  400    // padded smem row bytes: 192 cols * 2B + 16 pad (400 % 128 == 16 -> ldmatrix conflict-free)

// smem layout (byte offsets)
#define OFF_W   0          // W fp16 [512 x 192(+pad)] : 512*400 = 204800 B
#define OFF_Z   204800     // Z fp16 double-buffered [2][32 x 192(+pad)] : 2*12800 B
#define ZBUF    12800
#define OFF_XN  230400     // xn[32]
#define SMEM_DYN (230400 + 128 + 128)

__device__ float g_h[NTASK * 128];   // final hidden states (original task order)

static __device__ __forceinline__ float tanh_f(float x) {
    float y; asm("tanh.approx.f32 %0, %1;" : "=f"(y) : "f"(x)); return y;
}
static __device__ __forceinline__ float sigm_f(float x) {
    return fmaf(tanh_f(0.5f * x), 0.5f, 0.5f);
}

#define LDSM4(r0,r1,r2,r3,addr) \
    asm volatile("ldmatrix.sync.aligned.m8n8.x4.shared.b16 {%0,%1,%2,%3}, [%4];" \
        : "=r"(r0), "=r"(r1), "=r"(r2), "=r"(r3) : "r"(addr))
#define LDSM2(r0,r1,addr) \
    asm volatile("ldmatrix.sync.aligned.m8n8.x2.shared.b16 {%0,%1}, [%2];" \
        : "=r"(r0), "=r"(r1) : "r"(addr))
#define MMA16816(d,a,b) \
    asm volatile("mma.sync.aligned.m16n8k16.row.col.f32.f16.f16.f32 " \
        "{%0,%1,%2,%3}, {%4,%5,%6,%7}, {%8,%9}, {%0,%1,%2,%3};" \
        : "+f"((d)[0]), "+f"((d)[1]), "+f"((d)[2]), "+f"((d)[3]) \
        : "r"((a)[0]), "r"((a)[1]), "r"((a)[2]), "r"((a)[3]), "r"((b)[0]), "r"((b)[1]))

__global__ void __launch_bounds__(256, 1) lstm_kernel(
    const float* __restrict__ xw, const int* __restrict__ xn,
    const float* __restrict__ W_ih, const float* __restrict__ W_hh,
    const float* __restrict__ b_ih, const float* __restrict__ b_hh)
{
    extern __shared__ __align__(128) char sm[];
    const uint32_t s0 = (uint32_t)__cvta_generic_to_shared(sm);
    const int tid = threadIdx.x, wid = tid >> 5, lane = tid & 31;
    const int task0 = blockIdx.x * RPC;

    // ---- load W = [W_hh | W_ih] fp16, row-major, padded rows ----
    for (int i = tid; i < 512 * 128; i += 256) {
        int row = i >> 7, col = i & 127;
        *(__half*)(sm + OFF_W + row * ROWB + col * 2) = __float2half_rn(W_hh[i]);
    }
    for (int i = tid; i < 512 * 64; i += 256) {
        int row = i >> 6, col = i & 63;
        *(__half*)(sm + OFF_W + row * ROWB + 256 + col * 2) = __float2half_rn(W_ih[i]);
    }
    // zero both Z buffers (h0 = 0)
    for (int i = tid; i < (2 * ZBUF) / 4; i += 256) ((uint32_t*)(sm + OFF_Z))[i] = 0u;
    if (tid < RPC) ((int*)(sm + OFF_XN))[tid] = min(max(xn[task0 + tid], 1), 512);
    __syncthreads();

    const int* xns = (const int*)(sm + OFF_XN);
    int tmax = 1;
    #pragma unroll 8
    for (int r = 0; r < RPC; r++) { int v = xns[r]; tmax = v > tmax ? v : tmax; }

    // biases folded into accumulator init; j0/j0+8 are this thread's two hidden rows
    const int j0 = wid * 16 + (lane >> 2);
    float B0[4], B1[4];
    #pragma unroll
    for (int g = 0; g < 4; g++) {
        B0[g] = b_ih[g * 128 + j0]     + b_hh[g * 128 + j0];
        B1[g] = b_ih[g * 128 + j0 + 8] + b_hh[g * 128 + j0 + 8];
    }
    int nwc[8];
    #pragma unroll
    for (int nt = 0; nt < 4; nt++)
        #pragma unroll
        for (int b = 0; b < 2; b++)
            nwc[nt * 2 + b] = xns[nt * 8 + (lane & 3) * 2 + b];
    float cst[16];
    #pragma unroll
    for (int i = 0; i < 16; i++) cst[i] = 0.f;

    // x staging mapping: thread -> (task row sr, 8-float chunk sch)
    const int sr = tid >> 3, sch = tid & 7;
    const float* xptr = xw + (size_t)(task0 + sr) * 512 * 64 + sch * 8;
    // stage x_0 into buffer 0
    {
        const float4* xp = (const float4*)xptr;
        float4 v0 = xp[0], v1 = xp[1];
        __half2 q0 = __floats2half2_rn(v0.x, v0.y), q1 = __floats2half2_rn(v0.z, v0.w);
        __half2 q2 = __floats2half2_rn(v1.x, v1.y), q3 = __floats2half2_rn(v1.z, v1.w);
        uint4 pk;
        pk.x = *(uint32_t*)&q0; pk.y = *(uint32_t*)&q1;
        pk.z = *(uint32_t*)&q2; pk.w = *(uint32_t*)&q3;
        *(uint4*)(sm + OFF_Z + sr * ROWB + 256 + sch * 16) = pk;
    }
    __syncthreads();

    // per-lane ldmatrix address components
    const uint32_t aOffLane = (uint32_t)((wid * 16 + (lane & 7) + ((lane >> 3) & 1) * 8) * ROWB
                                         + ((lane >> 4) & 1) * 16);
    const uint32_t bOffLane = (uint32_t)((lane & 7) * ROWB + ((lane >> 3) & 1) * 16);
    uint32_t zro = OFF_Z, zwo = OFF_Z + ZBUF;   // read / write buffer offsets

    for (int s = 0; s < tmax; ++s) {
        // accum init = biases
        float d[4][4][4];
        #pragma unroll
        for (int g = 0; g < 4; g++)
            #pragma unroll
            for (int nt = 0; nt < 4; nt++) {
                d[g][nt][0] = B0[g]; d[g][nt][1] = B0[g];
                d[g][nt][2] = B1[g]; d[g][nt][3] = B1[g];
            }

        const uint32_t aB = s0 + OFF_W + aOffLane;
        const uint32_t bB = s0 + zro + bOffLane;

        // gates[512,32] = W[512,192] @ Z[32,192]^T
        #pragma unroll
        for (int kt = 0; kt < 12; kt++) {
            uint32_t bf[4][2];
            #pragma unroll
            for (int nt = 0; nt < 4; nt++)
                LDSM2(bf[nt][0], bf[nt][1], bB + nt * 8 * ROWB + kt * 32);
            #pragma unroll
            for (int g = 0; g < 4; g++) {
                uint32_t a[4];
                LDSM4(a[0], a[1], a[2], a[3], aB + g * 128 * ROWB + kt * 32);
                #pragma unroll
                for (int nt = 0; nt < 4; nt++)
                    MMA16816(d[g][nt], a, bf[nt]);
            }
        }

        // epilogue: per-thread 16 LSTM cell updates, h -> next Z buffer
        #pragma unroll
        for (int nt = 0; nt < 4; nt++)
            #pragma unroll
            for (int b = 0; b < 2; b++) {
                const int nw = nwc[nt * 2 + b];
                const int c = nt * 8 + (lane & 3) * 2 + b;
                #pragma unroll
                for (int rr = 0; rr < 2; rr++) {
                    if (s < nw) {
                        const int k = rr * 2 + b;
                        float I = sigm_f(d[0][nt][k]);
                        float F = sigm_f(d[1][nt][k]);
                        float G = tanh_f(d[2][nt][k]);
                        float O = sigm_f(d[3][nt][k]);
                        const int ci = nt * 4 + rr * 2 + b;
                        float cc = fmaf(F, cst[ci], I * G);
                        cst[ci] = cc;
                        float h = O * tanh_f(cc);
                        const int j = j0 + rr * 8;
                        *(__half*)(sm + zwo + c * ROWB + j * 2) = __float2half_rn(h);
                        if (s == nw - 1) g_h[(size_t)(task0 + c) * 128 + j] = h;
                    }
                }
            }

        // stage x_{s+1} into write buffer
        if (s + 1 < tmax) {
            const float4* xp = (const float4*)(xptr + (size_t)(s + 1) * 64);
            float4 v0 = xp[0], v1 = xp[1];
            __half2 q0 = __floats2half2_rn(v0.x, v0.y), q1 = __floats2half2_rn(v0.z, v0.w);
            __half2 q2 = __floats2half2_rn(v1.x, v1.y), q3 = __floats2half2_rn(v1.z, v1.w);
            uint4 pk;
            pk.x = *(uint32_t*)&q0; pk.y = *(uint32_t*)&q1;
            pk.z = *(uint32_t*)&q2; pk.w = *(uint32_t*)&q3;
            *(uint4*)(sm + zwo + sr * ROWB + 256 + sch * 16) = pk;
        }
        __syncthreads();
        uint32_t t = zro; zro = zwo; zwo = t;
    }
}

// ---- kernel 2: h = [er, egw + bw]; y = h @ conv_w^T + conv_b; LayerNorm ----
__global__ void __launch_bounds__(256) conv_ln_kernel(
    const float* __restrict__ er, const float* __restrict__ egw,
    const float* __restrict__ conv_w, const float* __restrict__ conv_b,
    const float* __restrict__ ln_g, const float* __restrict__ ln_b,
    float* __restrict__ out)
{
    __shared__ float hin[16][256];
    __shared__ float ys[16][256];
    const int tid = threadIdx.x, lane = tid & 31, wid = tid >> 5;
    const int row0 = blockIdx.x * 16;

    for (int i = tid; i < 16 * 128; i += 256) {
        int rr = i >> 7, k = i & 127;
        size_t g = (size_t)(row0 + rr) * 128 + k;
        hin[rr][k]       = er[g];
        hin[rr][128 + k] = egw[g] + g_h[g];
    }
    __syncthreads();

    float acc[16];
    const float cbv = conv_b[tid];
    #pragma unroll
    for (int rr = 0; rr < 16; rr++) acc[rr] = cbv;

    const float4* wrow = (const float4*)(conv_w + (size_t)tid * 256);
    for (int k4 = 0; k4 < 64; k4++) {
        float4 w = wrow[k4];
        #pragma unroll
        for (int rr = 0; rr < 16; rr++) {
            float4 hv = *(const float4*)&hin[rr][k4 * 4];
            acc[rr] = fmaf(w.x, hv.x, acc[rr]);
            acc[rr] = fmaf(w.y, hv.y, acc[rr]);
            acc[rr] = fmaf(w.z, hv.z, acc[rr]);
            acc[rr] = fmaf(w.w, hv.w, acc[rr]);
        }
    }
    #pragma unroll
    for (int rr = 0; rr < 16; rr++) ys[rr][tid] = acc[rr];
    __syncthreads();

    #pragma unroll
    for (int t = 0; t < 2; t++) {
        int rr = wid * 2 + t;
        float s1 = 0.f, s2 = 0.f;
        #pragma unroll
        for (int m = 0; m < 8; m++) { float v = ys[rr][lane + m * 32]; s1 += v; s2 += v * v; }
        #pragma unroll
        for (int o = 16; o > 0; o >>= 1) {
            s1 += __shfl_xor_sync(0xFFFFFFFFu, s1, o);
            s2 += __shfl_xor_sync(0xFFFFFFFFu, s2, o);
        }
        float mu  = s1 * (1.f / 256.f);
        float var = s2 * (1.f / 256.f) - mu * mu;
        float inv = rsqrtf(var + 1e-5f);
        size_t ob = (size_t)(row0 + rr) * 256;
        #pragma unroll
        for (int m = 0; m < 8; m++) {
            int k = lane + m * 32;
            out[ob + k] = (ys[rr][k] - mu) * inv * ln_g[k] + ln_b[k];
        }
    }
}

extern "C" void kernel_launch(void* const* d_in, const int* in_sizes, int n_in,
                              void* d_out, int out_size)
{
    const float* xw     = (const float*)d_in[0];
    const int*   xn     = (const int*)  d_in[1];
    const float* er     = (const float*)d_in[2];
    const float* egw    = (const float*)d_in[3];
    const float* W_ih   = (const float*)d_in[4];
    const float* W_hh   = (const float*)d_in[5];
    const float* b_ih   = (const float*)d_in[6];
    const float* b_hh   = (const float*)d_in[7];
    const float* conv_w = (const float*)d_in[8];
    const float* conv_b = (const float*)d_in[9];
    const float* ln_g   = (const float*)d_in[10];
    const float* ln_b   = (const float*)d_in[11];
    float* out = (float*)d_out;

    cudaFuncSetAttribute(lstm_kernel, cudaFuncAttributeMaxDynamicSharedMemorySize, SMEM_DYN);
    lstm_kernel<<<NCTA, 256, SMEM_DYN>>>(xw, xn, W_ih, W_hh, b_ih, b_hh);
    conv_ln_kernel<<<NTASK / 16, 256>>>(er, egw, conv_w, conv_b, ln_g, ln_b, out);
}

// round 3
// speedup vs baseline: 1.2072x; 1.2072x over previous
#include <cuda_runtime.h>
#include <cuda_fp16.h>
#include <cstdint>
#include <cstddef>

// Problem constants
#define NTASK 4096   // BS*SL tasks
#define RPC   32     // tasks per CTA
#define NCTA  128    // NTASK / RPC
#define ROWB  400    // padded smem row bytes: 192 cols * 2B + 16 pad (400 % 128 == 16 -> ldmatrix conflict-free)

// smem layout (byte offsets)
#define OFF_W   0          // W fp16 [512 x 192(+pad)] : 512*400 = 204800 B
#define OFF_Z   204800     // Z fp16 double-buffered [2][32 x 192(+pad)] : 2*12800 B
#define ZBUF    12800
#define OFF_XN  230400     // xn[32]
#define SMEM_DYN (230400 + 128 + 128)

__device__ float g_h[NTASK * 128];   // final hidden states (original task order)

static __device__ __forceinline__ float tanh_f(float x) {
    float y; asm("tanh.approx.f32 %0, %1;" : "=f"(y) : "f"(x)); return y;
}
static __device__ __forceinline__ float sigm_f(float x) {
    return fmaf(tanh_f(0.5f * x), 0.5f, 0.5f);
}

#define LDSM4(r0,r1,r2,r3,addr) \
    asm volatile("ldmatrix.sync.aligned.m8n8.x4.shared.b16 {%0,%1,%2,%3}, [%4];" \
        : "=r"(r0), "=r"(r1), "=r"(r2), "=r"(r3) : "r"(addr))
#define LDSM2(r0,r1,addr) \
    asm volatile("ldmatrix.sync.aligned.m8n8.x2.shared.b16 {%0,%1}, [%2];" \
        : "=r"(r0), "=r"(r1) : "r"(addr))
#define MMA16816(d,a,b) \
    asm volatile("mma.sync.aligned.m16n8k16.row.col.f32.f16.f16.f32 " \
        "{%0,%1,%2,%3}, {%4,%5,%6,%7}, {%8,%9}, {%0,%1,%2,%3};" \
        : "+f"((d)[0]), "+f"((d)[1]), "+f"((d)[2]), "+f"((d)[3]) \
        : "r"((a)[0]), "r"((a)[1]), "r"((a)[2]), "r"((a)[3]), "r"((b)[0]), "r"((b)[1]))

__global__ void __launch_bounds__(256, 1) lstm_kernel(
    const float* __restrict__ xw, const int* __restrict__ xn,
    const float* __restrict__ W_ih, const float* __restrict__ W_hh,
    const float* __restrict__ b_ih, const float* __restrict__ b_hh)
{
    extern __shared__ __align__(128) char sm[];
    const uint32_t s0 = (uint32_t)__cvta_generic_to_shared(sm);
    const int tid = threadIdx.x, wid = tid >> 5, lane = tid & 31;
    const int task0 = blockIdx.x * RPC;

    // ---- load W = [W_hh | W_ih] fp16, row-major, padded rows ----
    for (int i = tid; i < 512 * 128; i += 256) {
        int row = i >> 7, col = i & 127;
        *(__half*)(sm + OFF_W + row * ROWB + col * 2) = __float2half_rn(W_hh[i]);
    }
    for (int i = tid; i < 512 * 64; i += 256) {
        int row = i >> 6, col = i & 63;
        *(__half*)(sm + OFF_W + row * ROWB + 256 + col * 2) = __float2half_rn(W_ih[i]);
    }
    // zero both Z buffers (h0 = 0)
    for (int i = tid; i < (2 * ZBUF) / 4; i += 256) ((uint32_t*)(sm + OFF_Z))[i] = 0u;
    if (tid < RPC) ((int*)(sm + OFF_XN))[tid] = min(max(xn[task0 + tid], 1), 512);
    __syncthreads();

    const int* xns = (const int*)(sm + OFF_XN);
    int tmax = 1;
    #pragma unroll 8
    for (int r = 0; r < RPC; r++) { int v = xns[r]; tmax = v > tmax ? v : tmax; }

    // biases folded into accumulator init; j0/j0+8 are this thread's two hidden rows
    const int j0 = wid * 16 + (lane >> 2);
    float B0[4], B1[4];
    #pragma unroll
    for (int g = 0; g < 4; g++) {
        B0[g] = b_ih[g * 128 + j0]     + b_hh[g * 128 + j0];
        B1[g] = b_ih[g * 128 + j0 + 8] + b_hh[g * 128 + j0 + 8];
    }
    int nwc[8];
    #pragma unroll
    for (int nt = 0; nt < 4; nt++)
        #pragma unroll
        for (int b = 0; b < 2; b++)
            nwc[nt * 2 + b] = xns[nt * 8 + (lane & 3) * 2 + b];
    float cst[16];
    #pragma unroll
    for (int i = 0; i < 16; i++) cst[i] = 0.f;

    // x staging mapping: thread -> (task row sr, 8-float chunk sch)
    const int sr = tid >> 3, sch = tid & 7;
    const float* xptr = xw + (size_t)(task0 + sr) * 512 * 64 + sch * 8;
    const uint32_t zxBase = (uint32_t)(sr * ROWB + 256 + sch * 16);
    // stage x_0 into buffer 0
    {
        const float4* xp = (const float4*)xptr;
        float4 v0 = xp[0], v1 = xp[1];
        __half2 q0 = __floats2half2_rn(v0.x, v0.y), q1 = __floats2half2_rn(v0.z, v0.w);
        __half2 q2 = __floats2half2_rn(v1.x, v1.y), q3 = __floats2half2_rn(v1.z, v1.w);
        uint4 pk;
        pk.x = *(uint32_t*)&q0; pk.y = *(uint32_t*)&q1;
        pk.z = *(uint32_t*)&q2; pk.w = *(uint32_t*)&q3;
        *(uint4*)(sm + OFF_Z + zxBase) = pk;
    }
    __syncthreads();

    // per-lane ldmatrix address components
    const uint32_t aOffLane = (uint32_t)((wid * 16 + (lane & 7) + ((lane >> 3) & 1) * 8) * ROWB
                                         + ((lane >> 4) & 1) * 16);
    const uint32_t bOffLane = (uint32_t)((lane & 7) * ROWB + ((lane >> 3) & 1) * 16);
    uint32_t zro = OFF_Z, zwo = OFF_Z + ZBUF;   // read / write buffer offsets

    for (int s = 0; s < tmax; ++s) {
        // ---- PREFETCH x_{s+1} at the TOP of the step: the LDG's DRAM latency is
        //      covered by the MMA + epilogue below; only cvt+STS remain before the
        //      barrier (which drains pending STS, so the STS must not depend on a
        //      fresh LDG there).
        float4 v0, v1;
        const bool pf = (s + 1 < tmax);
        if (pf) {
            const float4* xp = (const float4*)(xptr + (size_t)(s + 1) * 64);
            v0 = xp[0]; v1 = xp[1];
        }

        // accum init = biases
        float d[4][4][4];
        #pragma unroll
        for (int g = 0; g < 4; g++)
            #pragma unroll
            for (int nt = 0; nt < 4; nt++) {
                d[g][nt][0] = B0[g]; d[g][nt][1] = B0[g];
                d[g][nt][2] = B1[g]; d[g][nt][3] = B1[g];
            }

        const uint32_t aB = s0 + OFF_W + aOffLane;
        const uint32_t bB = s0 + zro + bOffLane;

        // gates[512,32] = W[512,192] @ Z[32,192]^T
        #pragma unroll
        for (int kt = 0; kt < 12; kt++) {
            uint32_t bf[4][2];
            #pragma unroll
            for (int nt = 0; nt < 4; nt++)
                LDSM2(bf[nt][0], bf[nt][1], bB + nt * 8 * ROWB + kt * 32);
            #pragma unroll
            for (int g = 0; g < 4; g++) {
                uint32_t a[4];
                LDSM4(a[0], a[1], a[2], a[3], aB + g * 128 * ROWB + kt * 32);
                #pragma unroll
                for (int nt = 0; nt < 4; nt++)
                    MMA16816(d[g][nt], a, bf[nt]);
            }
        }

        // epilogue: per-thread 16 LSTM cell updates, h -> next Z buffer.
        // All 4 activations issued before the dependent c/h chain for MUFU ILP.
        #pragma unroll
        for (int nt = 0; nt < 4; nt++)
            #pragma unroll
            for (int b = 0; b < 2; b++) {
                const int nw = nwc[nt * 2 + b];
                const int c = nt * 8 + (lane & 3) * 2 + b;
                #pragma unroll
                for (int rr = 0; rr < 2; rr++) {
                    if (s < nw) {
                        const int k = rr * 2 + b;
                        float I = sigm_f(d[0][nt][k]);
                        float F = sigm_f(d[1][nt][k]);
                        float G = tanh_f(d[2][nt][k]);
                        float O = sigm_f(d[3][nt][k]);
                        const int ci = nt * 4 + rr * 2 + b;
                        float cc = fmaf(F, cst[ci], I * G);
                        cst[ci] = cc;
                        float h = O * tanh_f(cc);
                        const int j = j0 + rr * 8;
                        *(__half*)(sm + zwo + c * ROWB + j * 2) = __float2half_rn(h);
                        if (s == nw - 1) g_h[(size_t)(task0 + c) * 128 + j] = h;
                    }
                }
            }

        // stage prefetched x_{s+1} into write buffer (registers -> cvt -> STS; no LDG here)
        if (pf) {
            __half2 q0 = __floats2half2_rn(v0.x, v0.y), q1 = __floats2half2_rn(v0.z, v0.w);
            __half2 q2 = __floats2half2_rn(v1.x, v1.y), q3 = __floats2half2_rn(v1.z, v1.w);
            uint4 pk;
            pk.x = *(uint32_t*)&q0; pk.y = *(uint32_t*)&q1;
            pk.z = *(uint32_t*)&q2; pk.w = *(uint32_t*)&q3;
            *(uint4*)(sm + zwo + zxBase) = pk;
        }
        __syncthreads();
        uint32_t t = zro; zro = zwo; zwo = t;
    }
}

// ---- kernel 2: h = [er, egw + bw]; y = h @ conv_w^T + conv_b; LayerNorm ----
__global__ void __launch_bounds__(256) conv_ln_kernel(
    const float* __restrict__ er, const float* __restrict__ egw,
    const float* __restrict__ conv_w, const float* __restrict__ conv_b,
    const float* __restrict__ ln_g, const float* __restrict__ ln_b,
    float* __restrict__ out)
{
    __shared__ float hin[16][256];
    __shared__ float ys[16][256];
    const int tid = threadIdx.x, lane = tid & 31, wid = tid >> 5;
    const int row0 = blockIdx.x * 16;

    for (int i = tid; i < 16 * 128; i += 256) {
        int rr = i >> 7, k = i & 127;
        size_t g = (size_t)(row0 + rr) * 128 + k;
        hin[rr][k]       = er[g];
        hin[rr][128 + k] = egw[g] + g_h[g];
    }
    __syncthreads();

    float acc[16];
    const float cbv = conv_b[tid];
    #pragma unroll
    for (int rr = 0; rr < 16; rr++) acc[rr] = cbv;

    const float4* wrow = (const float4*)(conv_w + (size_t)tid * 256);
    for (int k4 = 0; k4 < 64; k4++) {
        float4 w = wrow[k4];
        #pragma unroll
        for (int rr = 0; rr < 16; rr++) {
            float4 hv = *(const float4*)&hin[rr][k4 * 4];
            acc[rr] = fmaf(w.x, hv.x, acc[rr]);
            acc[rr] = fmaf(w.y, hv.y, acc[rr]);
            acc[rr] = fmaf(w.z, hv.z, acc[rr]);
            acc[rr] = fmaf(w.w, hv.w, acc[rr]);
        }
    }
    #pragma unroll
    for (int rr = 0; rr < 16; rr++) ys[rr][tid] = acc[rr];
    __syncthreads();

    #pragma unroll
    for (int t = 0; t < 2; t++) {
        int rr = wid * 2 + t;
        float s1 = 0.f, s2 = 0.f;
        #pragma unroll
        for (int m = 0; m < 8; m++) { float v = ys[rr][lane + m * 32]; s1 += v; s2 += v * v; }
        #pragma unroll
        for (int o = 16; o > 0; o >>= 1) {
            s1 += __shfl_xor_sync(0xFFFFFFFFu, s1, o);
            s2 += __shfl_xor_sync(0xFFFFFFFFu, s2, o);
        }
        float mu  = s1 * (1.f / 256.f);
        float var = s2 * (1.f / 256.f) - mu * mu;
        float inv = rsqrtf(var + 1e-5f);
        size_t ob = (size_t)(row0 + rr) * 256;
        #pragma unroll
        for (int m = 0; m < 8; m++) {
            int k = lane + m * 32;
            out[ob + k] = (ys[rr][k] - mu) * inv * ln_g[k] + ln_b[k];
        }
    }
}

extern "C" void kernel_launch(void* const* d_in, const int* in_sizes, int n_in,
                              void* d_out, int out_size)
{
    const float* xw     = (const float*)d_in[0];
    const int*   xn     = (const int*)  d_in[1];
    const float* er     = (const float*)d_in[2];
    const float* egw    = (const float*)d_in[3];
    const float* W_ih   = (const float*)d_in[4];
    const float* W_hh   = (const float*)d_in[5];
    const float* b_ih   = (const float*)d_in[6];
    const float* b_hh   = (const float*)d_in[7];
    const float* conv_w = (const float*)d_in[8];
    const float* conv_b = (const float*)d_in[9];
    const float* ln_g   = (const float*)d_in[10];
    const float* ln_b   = (const float*)d_in[11];
    float* out = (float*)d_out;

    cudaFuncSetAttribute(lstm_kernel, cudaFuncAttributeMaxDynamicSharedMemorySize, SMEM_DYN);
    lstm_kernel<<<NCTA, 256, SMEM_DYN>>>(xw, xn, W_ih, W_hh, b_ih, b_hh);
    conv_ln_kernel<<<NTASK / 16, 256>>>(er, egw, conv_w, conv_b, ln_g, ln_b, out);
}

// round 4
// speedup vs baseline: 1.4579x; 1.2077x over previous
#include <cuda_runtime.h>
#include <cuda_fp16.h>
#include <cstdint>
#include <cstddef>

// Problem constants
#define NTASK 4096   // BS*SL tasks
#define RPC   32     // tasks per CTA
#define NCTA  128    // NTASK / RPC
#define ROWB  400    // padded smem row bytes: 192 cols * 2B + 16 pad (400 % 128 == 16 -> ldmatrix conflict-free)

// smem layout (byte offsets)
#define OFF_W   0          // W fp16 [512 x 192(+pad)] : 512*400 = 204800 B
#define OFF_Z   204800     // Z fp16 double-buffered [2][32 x 192(+pad)] : 2*12800 B
#define ZBUF    12800
#define OFF_XN  230400     // raw xn[32]
#define OFF_SNW 230528     // sorted nw[32] (desc)
#define OFF_SOR 230656     // sorted->orig index[32]
#define SMEM_DYN (230656 + 128)

__device__ float g_h[NTASK * 128];   // final hidden states (original task order)

static __device__ __forceinline__ float tanh_f(float x) {
    float y; asm("tanh.approx.f32 %0, %1;" : "=f"(y) : "f"(x)); return y;
}
static __device__ __forceinline__ float sigm_f(float x) {
    return fmaf(tanh_f(0.5f * x), 0.5f, 0.5f);
}

#define LDSM4(r0,r1,r2,r3,addr) \
    asm volatile("ldmatrix.sync.aligned.m8n8.x4.shared.b16 {%0,%1,%2,%3}, [%4];" \
        : "=r"(r0), "=r"(r1), "=r"(r2), "=r"(r3) : "r"(addr))
#define LDSM2(r0,r1,addr) \
    asm volatile("ldmatrix.sync.aligned.m8n8.x2.shared.b16 {%0,%1}, [%2];" \
        : "=r"(r0), "=r"(r1) : "r"(addr))
#define MMA16816(d,a,b) \
    asm volatile("mma.sync.aligned.m16n8k16.row.col.f32.f16.f16.f32 " \
        "{%0,%1,%2,%3}, {%4,%5,%6,%7}, {%8,%9}, {%0,%1,%2,%3};" \
        : "+f"((d)[0]), "+f"((d)[1]), "+f"((d)[2]), "+f"((d)[3]) \
        : "r"((a)[0]), "r"((a)[1]), "r"((a)[2]), "r"((a)[3]), "r"((b)[0]), "r"((b)[1]))

// One full step at NT active 8-task tiles (tiles are a prefix after the sort).
// References enclosing-scope: s, aB, bB, zwo, sm, lane, j0, task0, B0, B1, cst, nwc, oid.
#define STEP_BODY(NT) do {                                                        \
    float d[4][NT][4];                                                            \
    _Pragma("unroll")                                                             \
    for (int g_ = 0; g_ < 4; g_++) {                                              \
      _Pragma("unroll")                                                           \
      for (int nt_ = 0; nt_ < NT; nt_++) {                                        \
        d[g_][nt_][0] = B0[g_]; d[g_][nt_][1] = B0[g_];                           \
        d[g_][nt_][2] = B1[g_]; d[g_][nt_][3] = B1[g_];                           \
      } }                                                                         \
    _Pragma("unroll")                                                             \
    for (int kt_ = 0; kt_ < 12; kt_++) {                                          \
      uint32_t bf_[NT][2];                                                        \
      _Pragma("unroll")                                                           \
      for (int nt_ = 0; nt_ < NT; nt_++)                                          \
        LDSM2(bf_[nt_][0], bf_[nt_][1], bB + nt_ * 8 * ROWB + kt_ * 32);          \
      _Pragma("unroll")                                                           \
      for (int g_ = 0; g_ < 4; g_++) {                                            \
        uint32_t a_[4];                                                           \
        LDSM4(a_[0], a_[1], a_[2], a_[3], aB + g_ * 128 * ROWB + kt_ * 32);       \
        _Pragma("unroll")                                                         \
        for (int nt_ = 0; nt_ < NT; nt_++)                                        \
          MMA16816(d[g_][nt_], a_, bf_[nt_]);                                     \
      } }                                                                         \
    _Pragma("unroll")                                                             \
    for (int nt_ = 0; nt_ < NT; nt_++) {                                          \
      _Pragma("unroll")                                                           \
      for (int b_ = 0; b_ < 2; b_++) {                                            \
        const int nw_ = nwc[nt_ * 2 + b_];                                        \
        const int c_ = nt_ * 8 + (lane & 3) * 2 + b_;                             \
        _Pragma("unroll")                                                         \
        for (int rr_ = 0; rr_ < 2; rr_++) {                                       \
          if (s < nw_) {                                                          \
            const int k_ = rr_ * 2 + b_;                                          \
            float I_ = sigm_f(d[0][nt_][k_]);                                     \
            float F_ = sigm_f(d[1][nt_][k_]);                                     \
            float G_ = tanh_f(d[2][nt_][k_]);                                     \
            float O_ = sigm_f(d[3][nt_][k_]);                                     \
            const int ci_ = nt_ * 4 + rr_ * 2 + b_;                               \
            float cc_ = fmaf(F_, cst[ci_], I_ * G_);                              \
            cst[ci_] = cc_;                                                       \
            float h_ = O_ * tanh_f(cc_);                                          \
            const int j_ = j0 + rr_ * 8;                                          \
            *(__half*)(sm + zwo + c_ * ROWB + j_ * 2) = __float2half_rn(h_);      \
            if (s == nw_ - 1)                                                     \
              g_h[(size_t)(task0 + oid[nt_ * 2 + b_]) * 128 + j_] = h_;           \
          } } } }                                                                 \
  } while (0)

__global__ void __launch_bounds__(256, 1) lstm_kernel(
    const float* __restrict__ xw, const int* __restrict__ xn,
    const float* __restrict__ W_ih, const float* __restrict__ W_hh,
    const float* __restrict__ b_ih, const float* __restrict__ b_hh)
{
    extern __shared__ __align__(128) char sm[];
    const uint32_t s0 = (uint32_t)__cvta_generic_to_shared(sm);
    const int tid = threadIdx.x, wid = tid >> 5, lane = tid & 31;
    const int task0 = blockIdx.x * RPC;

    // ---- load W = [W_hh | W_ih] fp16, row-major, padded rows ----
    for (int i = tid; i < 512 * 128; i += 256) {
        int row = i >> 7, col = i & 127;
        *(__half*)(sm + OFF_W + row * ROWB + col * 2) = __float2half_rn(W_hh[i]);
    }
    for (int i = tid; i < 512 * 64; i += 256) {
        int row = i >> 6, col = i & 63;
        *(__half*)(sm + OFF_W + row * ROWB + 256 + col * 2) = __float2half_rn(W_ih[i]);
    }
    // zero both Z buffers (h0 = 0)
    for (int i = tid; i < (2 * ZBUF) / 4; i += 256) ((uint32_t*)(sm + OFF_Z))[i] = 0u;
    if (tid < RPC) ((int*)(sm + OFF_XN))[tid] = min(max(xn[task0 + tid], 1), 512);
    __syncthreads();

    // ---- rank-sort the 32 tasks by nw (desc), ties by index ----
    {
        const int* raw = (const int*)(sm + OFF_XN);
        if (tid < RPC) {
            const int my = raw[tid];
            int r = 0;
            #pragma unroll 8
            for (int jj = 0; jj < RPC; jj++) {
                int vj = raw[jj];
                r += (vj > my) || (vj == my && jj < tid);
            }
            ((int*)(sm + OFF_SNW))[r] = my;
            ((int*)(sm + OFF_SOR))[r] = tid;
        }
    }
    __syncthreads();

    const int* snw  = (const int*)(sm + OFF_SNW);
    const int* sorg = (const int*)(sm + OFF_SOR);
    const int tmax = snw[0];
    const int tm1 = snw[8], tm2 = snw[16], tm3 = snw[24];

    // biases folded into accumulator init; j0/j0+8 are this thread's two hidden rows
    const int j0 = wid * 16 + (lane >> 2);
    float B0[4], B1[4];
    #pragma unroll
    for (int g = 0; g < 4; g++) {
        B0[g] = b_ih[g * 128 + j0]     + b_hh[g * 128 + j0];
        B1[g] = b_ih[g * 128 + j0 + 8] + b_hh[g * 128 + j0 + 8];
    }
    // per-thread task metadata in SORTED order: sorted position c = nt*8 + (lane&3)*2 + b
    int nwc[8], oid[8];
    #pragma unroll
    for (int nt = 0; nt < 4; nt++)
        #pragma unroll
        for (int b = 0; b < 2; b++) {
            const int c = nt * 8 + (lane & 3) * 2 + b;
            nwc[nt * 2 + b] = snw[c];
            oid[nt * 2 + b] = sorg[c];
        }
    float cst[16];
    #pragma unroll
    for (int i = 0; i < 16; i++) cst[i] = 0.f;

    // x staging mapping: thread -> (sorted task row sr, 8-float chunk sch); source uses orig id
    const int sr = tid >> 3, sch = tid & 7;
    const float* xptr = xw + (size_t)(task0 + sorg[sr]) * 512 * 64 + sch * 8;
    const uint32_t zxBase = (uint32_t)(sr * ROWB + 256 + sch * 16);
    // stage x_0 into buffer 0
    {
        const float4* xp = (const float4*)xptr;
        float4 v0 = xp[0], v1 = xp[1];
        __half2 q0 = __floats2half2_rn(v0.x, v0.y), q1 = __floats2half2_rn(v0.z, v0.w);
        __half2 q2 = __floats2half2_rn(v1.x, v1.y), q3 = __floats2half2_rn(v1.z, v1.w);
        uint4 pk;
        pk.x = *(uint32_t*)&q0; pk.y = *(uint32_t*)&q1;
        pk.z = *(uint32_t*)&q2; pk.w = *(uint32_t*)&q3;
        *(uint4*)(sm + OFF_Z + zxBase) = pk;
    }
    __syncthreads();

    // per-lane ldmatrix address components
    const uint32_t aOffLane = (uint32_t)((wid * 16 + (lane & 7) + ((lane >> 3) & 1) * 8) * ROWB
                                         + ((lane >> 4) & 1) * 16);
    const uint32_t bOffLane = (uint32_t)((lane & 7) * ROWB + ((lane >> 3) & 1) * 16);
    uint32_t zro = OFF_Z, zwo = OFF_Z + ZBUF;   // read / write buffer offsets

    for (int s = 0; s < tmax; ++s) {
        // prefetch x_{s+1} (LDG latency covered by MMA + epilogue below)
        float4 v0, v1;
        const bool pf = (s + 1 < tmax);
        if (pf) {
            const float4* xp = (const float4*)(xptr + (size_t)(s + 1) * 64);
            v0 = xp[0]; v1 = xp[1];
        }

        const uint32_t aB = s0 + OFF_W + aOffLane;
        const uint32_t bB = s0 + zro + bOffLane;

        // active 8-task tiles form a prefix (tasks sorted by nw desc)
        const int ntA = 1 + (s < tm1) + (s < tm2) + (s < tm3);
        switch (ntA) {
            case 4: STEP_BODY(4); break;
            case 3: STEP_BODY(3); break;
            case 2: STEP_BODY(2); break;
            default: STEP_BODY(1); break;
        }

        // stage prefetched x_{s+1} into write buffer (cvt+STS only before the barrier)
        if (pf) {
            __half2 q0 = __floats2half2_rn(v0.x, v0.y), q1 = __floats2half2_rn(v0.z, v0.w);
            __half2 q2 = __floats2half2_rn(v1.x, v1.y), q3 = __floats2half2_rn(v1.z, v1.w);
            uint4 pk;
            pk.x = *(uint32_t*)&q0; pk.y = *(uint32_t*)&q1;
            pk.z = *(uint32_t*)&q2; pk.w = *(uint32_t*)&q3;
            *(uint4*)(sm + zwo + zxBase) = pk;
        }
        __syncthreads();
        uint32_t t = zro; zro = zwo; zwo = t;
    }
}

// no-op kernel: shifts ncu's -s 5 -c 1 capture window onto lstm_kernel
__global__ void align_dummy_kernel() {}

// ---- kernel 2: h = [er, egw + bw]; y = h @ conv_w^T + conv_b; LayerNorm ----
__global__ void __launch_bounds__(256) conv_ln_kernel(
    const float* __restrict__ er, const float* __restrict__ egw,
    const float* __restrict__ conv_w, const float* __restrict__ conv_b,
    const float* __restrict__ ln_g, const float* __restrict__ ln_b,
    float* __restrict__ out)
{
    __shared__ float hin[16][256];
    __shared__ float ys[16][256];
    const int tid = threadIdx.x, lane = tid & 31, wid = tid >> 5;
    const int row0 = blockIdx.x * 16;

    for (int i = tid; i < 16 * 128; i += 256) {
        int rr = i >> 7, k = i & 127;
        size_t g = (size_t)(row0 + rr) * 128 + k;
        hin[rr][k]       = er[g];
        hin[rr][128 + k] = egw[g] + g_h[g];
    }
    __syncthreads();

    float acc[16];
    const float cbv = conv_b[tid];
    #pragma unroll
    for (int rr = 0; rr < 16; rr++) acc[rr] = cbv;

    const float4* wrow = (const float4*)(conv_w + (size_t)tid * 256);
    for (int k4 = 0; k4 < 64; k4++) {
        float4 w = wrow[k4];
        #pragma unroll
        for (int rr = 0; rr < 16; rr++) {
            float4 hv = *(const float4*)&hin[rr][k4 * 4];
            acc[rr] = fmaf(w.x, hv.x, acc[rr]);
            acc[rr] = fmaf(w.y, hv.y, acc[rr]);
            acc[rr] = fmaf(w.z, hv.z, acc[rr]);
            acc[rr] = fmaf(w.w, hv.w, acc[rr]);
        }
    }
    #pragma unroll
    for (int rr = 0; rr < 16; rr++) ys[rr][tid] = acc[rr];
    __syncthreads();

    #pragma unroll
    for (int t = 0; t < 2; t++) {
        int rr = wid * 2 + t;
        float s1 = 0.f, s2 = 0.f;
        #pragma unroll
        for (int m = 0; m < 8; m++) { float v = ys[rr][lane + m * 32]; s1 += v; s2 += v * v; }
        #pragma unroll
        for (int o = 16; o > 0; o >>= 1) {
            s1 += __shfl_xor_sync(0xFFFFFFFFu, s1, o);
            s2 += __shfl_xor_sync(0xFFFFFFFFu, s2, o);
        }
        float mu  = s1 * (1.f / 256.f);
        float var = s2 * (1.f / 256.f) - mu * mu;
        float inv = rsqrtf(var + 1e-5f);
        size_t ob = (size_t)(row0 + rr) * 256;
        #pragma unroll
        for (int m = 0; m < 8; m++) {
            int k = lane + m * 32;
            out[ob + k] = (ys[rr][k] - mu) * inv * ln_g[k] + ln_b[k];
        }
    }
}

extern "C" void kernel_launch(void* const* d_in, const int* in_sizes, int n_in,
                              void* d_out, int out_size)
{
    const float* xw     = (const float*)d_in[0];
    const int*   xn     = (const int*)  d_in[1];
    const float* er     = (const float*)d_in[2];
    const float* egw    = (const float*)d_in[3];
    const float* W_ih   = (const float*)d_in[4];
    const float* W_hh   = (const float*)d_in[5];
    const float* b_ih   = (const float*)d_in[6];
    const float* b_hh   = (const float*)d_in[7];
    const float* conv_w = (const float*)d_in[8];
    const float* conv_b = (const float*)d_in[9];
    const float* ln_g   = (const float*)d_in[10];
    const float* ln_b   = (const float*)d_in[11];
    float* out = (float*)d_out;

    cudaFuncSetAttribute(lstm_kernel, cudaFuncAttributeMaxDynamicSharedMemorySize, SMEM_DYN);
    // launch order D, L, C, D -> 6th executed launch overall is lstm_kernel,
    // which is what ncu (-s 5 -c 1) captures.
    align_dummy_kernel<<<1, 32>>>();
    lstm_kernel<<<NCTA, 256, SMEM_DYN>>>(xw, xn, W_ih, W_hh, b_ih, b_hh);
    conv_ln_kernel<<<NTASK / 16, 256>>>(er, egw, conv_w, conv_b, ln_g, ln_b, out);
    align_dummy_kernel<<<1, 32>>>();
}